// round 1
// baseline (speedup 1.0000x reference)
#include <cuda_runtime.h>
#include <cstdint>

#define NB    4
#define NCATT 8
#define ND    48
#define NH    128
#define NW    256
#define NCF   80
#define NEMB  64
#define NHW   (NH*NW)          // 32768

// Scratch (device globals: allocation-free contract)
__device__ float g_Q[NB*NEMB*NHW];      // 33.5 MB
__device__ float g_K[NB*NEMB*NHW];
__device__ float g_V[NB*NEMB*NHW];
__device__ float g_delta[NB*NCATT*NHW]; // 16.8 MB

#define FMA2(d, a, b2) asm("fma.rn.f32x2 %0, %1, %2, %3;" : "=l"(d) : "l"(a), "l"(b2), "l"(d))
#define PACK2(d, s)    asm("mov.b64 %0, {%1, %1};" : "=l"(d) : "f"(s))

// ---------------------------------------------------------------------------
// K1: QKV projection.  Out[192][n] = W[192][80] @ feat[80][n]  per batch.
// Register-blocked 8 rows x 8 pixels per thread, pixels packed in f32x2.
// ---------------------------------------------------------------------------
#define K1T 192
#define K1P 64

__global__ __launch_bounds__(K1T, 2)
void qkv_proj_kernel(const float* __restrict__ feat,
                     const float* __restrict__ Wq,
                     const float* __restrict__ Wk,
                     const float* __restrict__ Wv) {
    extern __shared__ float smem1[];
    float* wsh = smem1;               // [k=80][e=192]
    float* fsh = smem1 + NCF*192;     // [k=80][j=64]
    const int b   = blockIdx.y;
    const int n0  = blockIdx.x * K1P;
    const int tid = threadIdx.x;

    for (int idx = tid; idx < NCF*192; idx += K1T) {
        int k = idx / 192, e = idx - k*192;
        float v;
        if (e < 64)       v = Wq[e*NCF + k];
        else if (e < 128) v = Wk[(e-64)*NCF + k];
        else              v = Wv[(e-128)*NCF + k];
        wsh[idx] = v;
    }
    for (int idx = tid; idx < NCF*K1P; idx += K1T) {
        int k = idx >> 6, j = idx & 63;
        fsh[idx] = feat[(size_t)(b*NCF + k)*NHW + n0 + j];
    }
    __syncthreads();

    const int rg = tid >> 3;   // 0..23  -> output rows rg*8..rg*8+7
    const int pg = tid & 7;    // 0..7   -> pixels pg*8..pg*8+7

    unsigned long long acc[8][4];
#pragma unroll
    for (int r = 0; r < 8; r++)
#pragma unroll
        for (int j = 0; j < 4; j++) acc[r][j] = 0ull;

#pragma unroll 4
    for (int k = 0; k < NCF; k++) {
        const float4* wp = reinterpret_cast<const float4*>(&wsh[k*192 + rg*8]);
        float4 w0 = wp[0], w1 = wp[1];
        unsigned long long wd[8];
        PACK2(wd[0], w0.x); PACK2(wd[1], w0.y); PACK2(wd[2], w0.z); PACK2(wd[3], w0.w);
        PACK2(wd[4], w1.x); PACK2(wd[5], w1.y); PACK2(wd[6], w1.z); PACK2(wd[7], w1.w);
        const ulonglong2* fp = reinterpret_cast<const ulonglong2*>(&fsh[k*K1P + pg*8]);
        ulonglong2 f0 = fp[0], f1 = fp[1];
        unsigned long long fd[4];
        fd[0] = f0.x; fd[1] = f0.y; fd[2] = f1.x; fd[3] = f1.y;
#pragma unroll
        for (int r = 0; r < 8; r++)
#pragma unroll
            for (int j = 0; j < 4; j++)
                FMA2(acc[r][j], wd[r], fd[j]);
    }

#pragma unroll
    for (int r = 0; r < 8; r++) {
        int e  = rg*8 + r;                 // block boundaries (64,128) are multiples of 8
        float* dst = (e < 64) ? g_Q : ((e < 128) ? g_K : g_V);
        int ch = e & 63;
        ulonglong2* outp = reinterpret_cast<ulonglong2*>(
            &dst[(size_t)(b*NEMB + ch)*NHW + n0 + pg*8]);
        outp[0] = make_ulonglong2(acc[r][0], acc[r][1]);
        outp[1] = make_ulonglong2(acc[r][2], acc[r][3]);
    }
}

// ---------------------------------------------------------------------------
// K2: local windowed MHA with the torch-unfold MIXED channel/window view,
// softmax, context, out-projection (Wo), disparity mask -> g_delta.
// One thread per pixel; one shared tile buffer reused for K then V.
// Mixed mapping: for score[h][p], term d uses L = p*64 + h*16 + d,
//   channel e = L/9, window wi = L%9, neighbor (dy,dx) = (wi/3-1, wi%3-1).
// ---------------------------------------------------------------------------
#define T2 128
#define TW (T2+2)

__device__ __forceinline__ void load_tile(const float* __restrict__ src, float* sh,
                                          int b, int y, int x0, int tid) {
    const int TOT = NEMB*3*TW;   // 24960
    for (int idx = tid; idx < TOT; idx += T2) {
        int e   = idx / (3*TW);
        int rem = idx - e*(3*TW);
        int r   = rem / TW;
        int xx  = rem - r*TW;
        int gy = y + r - 1;
        int gx = x0 + xx - 1;
        float v = 0.0f;
        if ((unsigned)gy < NH && (unsigned)gx < NW)
            v = src[(size_t)(b*NEMB + e)*NHW + gy*NW + gx];
        sh[idx] = v;
    }
}

__global__ __launch_bounds__(T2, 2)
void attn_kernel(const float* __restrict__ dispgap, const float* __restrict__ Wo) {
    extern __shared__ float smem2[];
    float* sh    = smem2;               // [e=64][row=3][xx=130]
    float* wo_sh = smem2 + NEMB*3*TW;   // [a=8][q=64]
    const int b   = blockIdx.z;
    const int y   = blockIdx.y;
    const int x0  = blockIdx.x * T2;
    const int tid = threadIdx.x;
    const int x   = x0 + tid;

    for (int i = tid; i < NCATT*NEMB; i += T2) wo_sh[i] = Wo[i];
    load_tile(g_K, sh, b, y, x0, tid);
    __syncthreads();

    float Qr[64];
#pragma unroll
    for (int e = 0; e < 64; e++)
        Qr[e] = g_Q[(size_t)(b*NEMB + e)*NHW + y*NW + x];

    float sc[36];   // [h][p]
#pragma unroll
    for (int i = 0; i < 36; i++) sc[i] = 0.0f;

    // Pass 1: scores.  Loop order (d,p,h): consecutive FFMAs hit 36 distinct
    // accumulators -> full ILP.  All indices compile-time (LDS imm offsets).
#pragma unroll
    for (int d = 0; d < 16; d++)
#pragma unroll
        for (int p = 0; p < 9; p++)
#pragma unroll
            for (int h = 0; h < 4; h++) {
                const int q = h*16 + d;
                const int L = p*64 + q;
                const int e = L/9, wi = L % 9;
                const int dyy = wi/3, dxx = wi % 3;
                sc[h*9+p] += Qr[q] * sh[(e*3 + dyy)*TW + tid + dxx];
            }

    // Softmax over p (SCALE = 0.25 folded in, max-subtracted as in reference)
#pragma unroll
    for (int h = 0; h < 4; h++) {
        float m = sc[h*9];
#pragma unroll
        for (int p = 1; p < 9; p++) m = fmaxf(m, sc[h*9+p]);
        float s = 0.0f;
#pragma unroll
        for (int p = 0; p < 9; p++) {
            float ev = __expf(0.25f*(sc[h*9+p] - m));
            sc[h*9+p] = ev;
            s += ev;
        }
        float inv = __fdividef(1.0f, s);
#pragma unroll
        for (int p = 0; p < 9; p++) sc[h*9+p] *= inv;
    }

    __syncthreads();                    // pass-1 reads done
    load_tile(g_V, sh, b, y, x0, tid);  // reuse the same buffer for V
    __syncthreads();

    float ctx[64];
#pragma unroll
    for (int i = 0; i < 64; i++) ctx[i] = 0.0f;

    // Pass 2: context.  Loop order (p,d,h): inner 64 hit distinct ctx regs.
#pragma unroll
    for (int p = 0; p < 9; p++)
#pragma unroll
        for (int d = 0; d < 16; d++)
#pragma unroll
            for (int h = 0; h < 4; h++) {
                const int q = h*16 + d;
                const int L = p*64 + q;
                const int e = L/9, wi = L % 9;
                const int dyy = wi/3, dxx = wi % 3;
                ctx[q] += sc[h*9+p] * sh[(e*3 + dyy)*TW + tid + dxx];
            }

    // Out-projection: delta[a] = sum_q ctx[q] * Wo[a][q]
    float outv[8];
#pragma unroll
    for (int a = 0; a < 8; a++) outv[a] = 0.0f;
#pragma unroll
    for (int q = 0; q < 64; q++)
#pragma unroll
        for (int a = 0; a < 8; a++)
            outv[a] += ctx[q] * wo_sh[a*64 + q];

    const float dg = dispgap[b*NHW + y*NW + x];
    const bool zero = (dg >= 2.0f);
#pragma unroll
    for (int a = 0; a < 8; a++)
        g_delta[((b*NCATT + a)*NH + y)*NW + x] = zero ? 0.0f : outv[a];
}

// ---------------------------------------------------------------------------
// K3: out[b,a,d,y,x] = attn_vol[b,a,d,y,x] + delta[b,a,y,x]   (float4)
// ---------------------------------------------------------------------------
__global__ void add_kernel(const float* __restrict__ attn, float* __restrict__ out) {
    int i4 = blockIdx.x * blockDim.x + threadIdx.x;     // exact grid, no tail
    float4 a = reinterpret_cast<const float4*>(attn)[i4];
    int inner = i4 & (NHW/4 - 1);        // pixel-quad within (b,a,d) slice
    int bad   = i4 >> 13;                // (b*8+a)*48 + d
    int ba    = bad / ND;                // (b*8+a)
    float4 dl = reinterpret_cast<const float4*>(g_delta)[ba*(NHW/4) + inner];
    a.x += dl.x; a.y += dl.y; a.z += dl.z; a.w += dl.w;
    reinterpret_cast<float4*>(out)[i4] = a;
}

// ---------------------------------------------------------------------------
extern "C" void kernel_launch(void* const* d_in, const int* in_sizes, int n_in,
                              void* d_out, int out_size) {
    const float* attn_vol = (const float*)d_in[0];
    const float* feat     = (const float*)d_in[1];
    const float* dispgap  = (const float*)d_in[2];
    const float* Wq       = (const float*)d_in[3];
    const float* Wk       = (const float*)d_in[4];
    const float* Wv       = (const float*)d_in[5];
    const float* Wo       = (const float*)d_in[6];
    float* out = (float*)d_out;

    const int smem1 = (NCF*192 + NCF*K1P) * 4;          // 81920 B
    const int smem2 = (NEMB*3*TW + NCATT*NEMB) * 4;     // 101888 B
    cudaFuncSetAttribute(qkv_proj_kernel,
                         cudaFuncAttributeMaxDynamicSharedMemorySize, smem1);
    cudaFuncSetAttribute(attn_kernel,
                         cudaFuncAttributeMaxDynamicSharedMemorySize, smem2);

    qkv_proj_kernel<<<dim3(NHW/K1P, NB), K1T, smem1>>>(feat, Wq, Wk, Wv);
    attn_kernel<<<dim3(NW/T2, NH, NB), T2, smem2>>>(dispgap, Wo);
    add_kernel<<<(NB*NCATT*ND*NHW/4)/256, 256>>>(attn_vol, out);
}

// round 2
// speedup vs baseline: 1.1534x; 1.1534x over previous
#include <cuda_runtime.h>
#include <cstdint>

#define NB    4
#define NCATT 8
#define ND    48
#define NH    128
#define NW    256
#define NCF   80
#define NEMB  64
#define NHW   (NH*NW)          // 32768

// Scratch (device globals: allocation-free contract)
__device__ float g_Q[NB*NEMB*NHW];      // 33.5 MB
__device__ float g_K[NB*NEMB*NHW];
__device__ float g_V[NB*NEMB*NHW];
__device__ float g_delta[NB*NCATT*NHW]; // 16.8 MB

#define FMA2(d, a, b2) asm("fma.rn.f32x2 %0, %1, %2, %3;" : "=l"(d) : "l"(a), "l"(b2), "l"(d))
#define UNPACK2(lo, hi, d) asm("mov.b64 {%0, %1}, %2;" : "=f"(lo), "=f"(hi) : "l"(d))

// ---------------------------------------------------------------------------
// K1: QKV projection.  Out[192][n] = W[192][80] @ feat[80][n]  per batch.
// Row-pairs packed in f32x2 (consecutive rows adjacent in smem -> direct
// LDS.128, no MOVs); pixels pre-duplicated {f,f} in smem with 80B chunk
// padding for conflict-free LDS.  k-tiled (40) -> 56KB smem -> 3 blocks/SM.
// ---------------------------------------------------------------------------
#define K1T 192
#define K1P 64
#define KT  40

__global__ __launch_bounds__(K1T, 3)
void qkv_proj_kernel(const float* __restrict__ feat,
                     const float* __restrict__ Wq,
                     const float* __restrict__ Wk,
                     const float* __restrict__ Wv) {
    extern __shared__ float smem1[];
    float* wsh = smem1;                                  // [KT][192] floats
    unsigned long long* fsh =                            // [KT][8 grp][10 f32x2]
        reinterpret_cast<unsigned long long*>(smem1 + KT*192);
    const int b   = blockIdx.y;
    const int n0  = blockIdx.x * K1P;
    const int tid = threadIdx.x;
    const int rg  = tid >> 3;   // 0..23 -> rows rg*8..rg*8+7
    const int pg  = tid & 7;    // 0..7  -> pixels pg*8..pg*8+7

    unsigned long long acc[4][8];   // [row-pair][pixel]
#pragma unroll
    for (int r = 0; r < 4; r++)
#pragma unroll
        for (int j = 0; j < 8; j++) acc[r][j] = 0ull;

    for (int kt = 0; kt < NCF; kt += KT) {
        // weights: [k][e] column-major-in-e
        for (int idx = tid; idx < KT*192; idx += K1T) {
            int k = idx / 192, e = idx - k*192;
            int kk = kt + k;
            float v;
            if (e < 64)       v = Wq[e*NCF + kk];
            else if (e < 128) v = Wk[(e-64)*NCF + kk];
            else              v = Wv[(e-128)*NCF + kk];
            wsh[idx] = v;
        }
        // pixels, duplicated {f,f}, 10-slot (80B) padded chunks per pg group
        for (int idx = tid; idx < KT*K1P; idx += K1T) {
            int k = idx >> 6, j = idx & 63;
            float v = feat[(size_t)(b*NCF + kt + k)*NHW + n0 + j];
            float2 d2 = make_float2(v, v);
            fsh[k*80 + (j >> 3)*10 + (j & 7)] =
                *reinterpret_cast<unsigned long long*>(&d2);
        }
        __syncthreads();

#pragma unroll 4
        for (int k = 0; k < KT; k++) {
            const ulonglong2* wp =
                reinterpret_cast<const ulonglong2*>(&wsh[k*192 + rg*8]);
            ulonglong2 w0 = wp[0], w1 = wp[1];
            unsigned long long wd[4] = {w0.x, w0.y, w1.x, w1.y};
            const ulonglong2* fp =
                reinterpret_cast<const ulonglong2*>(&fsh[k*80 + pg*10]);
            ulonglong2 f0 = fp[0], f1 = fp[1], f2 = fp[2], f3 = fp[3];
            unsigned long long fd[8] = {f0.x, f0.y, f1.x, f1.y,
                                        f2.x, f2.y, f3.x, f3.y};
#pragma unroll
            for (int r = 0; r < 4; r++)
#pragma unroll
                for (int j = 0; j < 8; j++)
                    FMA2(acc[r][j], wd[r], fd[j]);
        }
        __syncthreads();
    }

#pragma unroll
    for (int r = 0; r < 4; r++) {
        const int e = rg*8 + r*2;          // rows e, e+1 (same segment: e even)
        float* base = (e < 64) ? g_Q : ((e < 128) ? g_K : g_V);
        const int ch = e & 63;
        float lo[8], hi[8];
#pragma unroll
        for (int j = 0; j < 8; j++) UNPACK2(lo[j], hi[j], acc[r][j]);
        size_t off = (size_t)(b*NEMB + ch)*NHW + n0 + pg*8;
        *reinterpret_cast<float4*>(&base[off])       = make_float4(lo[0],lo[1],lo[2],lo[3]);
        *reinterpret_cast<float4*>(&base[off+4])     = make_float4(lo[4],lo[5],lo[6],lo[7]);
        *reinterpret_cast<float4*>(&base[off+NHW])   = make_float4(hi[0],hi[1],hi[2],hi[3]);
        *reinterpret_cast<float4*>(&base[off+NHW+4]) = make_float4(hi[4],hi[5],hi[6],hi[7]);
    }
}

// ---------------------------------------------------------------------------
// K2: local windowed MHA with the torch-unfold MIXED channel/window view.
// Channel dimension split into two 32-channel chunks (mixed map splits
// exactly at L=288 <-> e=32) -> 52KB smem -> 3 blocks/SM.
// ---------------------------------------------------------------------------
#define T2  128
#define TW  (T2+2)
#define EC  32                 // channels per chunk
#define CHUNK_F (EC*3*TW)      // floats per chunk tile

__device__ __forceinline__ void load_tile32(const float* __restrict__ src, float* sh,
                                            int b, int e0, int y, int x0, int tid) {
    for (int idx = tid; idx < CHUNK_F; idx += T2) {
        int e   = idx / (3*TW);
        int rem = idx - e*(3*TW);
        int r   = rem / TW;
        int xx  = rem - r*TW;
        int gy = y + r - 1;
        int gx = x0 + xx - 1;
        float v = 0.0f;
        if ((unsigned)gy < NH && (unsigned)gx < NW)
            v = src[(size_t)(b*NEMB + e0 + e)*NHW + gy*NW + gx];
        sh[idx] = v;
    }
}

template<int E0>
__device__ __forceinline__ void score_chunk(const float* sh, float (&sc)[36],
                                            const float (&Qr)[64], int tid) {
#pragma unroll
    for (int d = 0; d < 16; d++)
#pragma unroll
        for (int p = 0; p < 9; p++)
#pragma unroll
            for (int h = 0; h < 4; h++) {
                const int q = h*16 + d;
                const int L = p*64 + q;
                const int e = L/9, wi = L % 9;
                if (e >= E0 && e < E0 + EC) {
                    const int dyy = wi/3, dxx = wi % 3;
                    sc[h*9+p] += Qr[q] * sh[((e-E0)*3 + dyy)*TW + tid + dxx];
                }
            }
}

template<int E0>
__device__ __forceinline__ void ctx_chunk(const float* sh, float (&ctx)[64],
                                          const float (&sc)[36], int tid) {
#pragma unroll
    for (int p = 0; p < 9; p++)
#pragma unroll
        for (int d = 0; d < 16; d++)
#pragma unroll
            for (int h = 0; h < 4; h++) {
                const int q = h*16 + d;
                const int L = p*64 + q;
                const int e = L/9, wi = L % 9;
                if (e >= E0 && e < E0 + EC) {
                    const int dyy = wi/3, dxx = wi % 3;
                    ctx[q] += sc[h*9+p] * sh[((e-E0)*3 + dyy)*TW + tid + dxx];
                }
            }
}

__global__ __launch_bounds__(T2, 3)
void attn_kernel(const float* __restrict__ dispgap, const float* __restrict__ Wo) {
    extern __shared__ float smem2[];
    float* sh    = smem2;               // [32][3][130]
    float* wo_sh = smem2 + CHUNK_F;     // [8][64]
    const int b   = blockIdx.z;
    const int y   = blockIdx.y;
    const int x0  = blockIdx.x * T2;
    const int tid = threadIdx.x;
    const int x   = x0 + tid;

    for (int i = tid; i < NCATT*NEMB; i += T2) wo_sh[i] = Wo[i];
    load_tile32(g_K, sh, b, 0, y, x0, tid);

    float Qr[64];
#pragma unroll
    for (int e = 0; e < 64; e++)
        Qr[e] = g_Q[(size_t)(b*NEMB + e)*NHW + y*NW + x];

    float sc[36];
#pragma unroll
    for (int i = 0; i < 36; i++) sc[i] = 0.0f;

    __syncthreads();
    score_chunk<0>(sh, sc, Qr, tid);
    __syncthreads();
    load_tile32(g_K, sh, b, 32, y, x0, tid);
    __syncthreads();
    score_chunk<32>(sh, sc, Qr, tid);

    // Softmax over p (SCALE = 0.25 folded in)
#pragma unroll
    for (int h = 0; h < 4; h++) {
        float m = sc[h*9];
#pragma unroll
        for (int p = 1; p < 9; p++) m = fmaxf(m, sc[h*9+p]);
        float s = 0.0f;
#pragma unroll
        for (int p = 0; p < 9; p++) {
            float ev = __expf(0.25f*(sc[h*9+p] - m));
            sc[h*9+p] = ev;
            s += ev;
        }
        float inv = __fdividef(1.0f, s);
#pragma unroll
        for (int p = 0; p < 9; p++) sc[h*9+p] *= inv;
    }

    float ctx[64];
#pragma unroll
    for (int i = 0; i < 64; i++) ctx[i] = 0.0f;

    __syncthreads();
    load_tile32(g_V, sh, b, 0, y, x0, tid);
    __syncthreads();
    ctx_chunk<0>(sh, ctx, sc, tid);
    __syncthreads();
    load_tile32(g_V, sh, b, 32, y, x0, tid);
    __syncthreads();
    ctx_chunk<32>(sh, ctx, sc, tid);

    // Out-projection
    float outv[8];
#pragma unroll
    for (int a = 0; a < 8; a++) outv[a] = 0.0f;
#pragma unroll
    for (int q = 0; q < 64; q++)
#pragma unroll
        for (int a = 0; a < 8; a++)
            outv[a] += ctx[q] * wo_sh[a*64 + q];

    const float dg = dispgap[b*NHW + y*NW + x];
    const bool zero = (dg >= 2.0f);
#pragma unroll
    for (int a = 0; a < 8; a++)
        g_delta[((b*NCATT + a)*NH + y)*NW + x] = zero ? 0.0f : outv[a];
}

// ---------------------------------------------------------------------------
// K3: out[b,a,d,y,x] = attn_vol[b,a,d,y,x] + delta[b,a,y,x]   (float4,
// streaming hints so delta stays L2-resident)
// ---------------------------------------------------------------------------
__global__ void add_kernel(const float* __restrict__ attn, float* __restrict__ out) {
    int i4 = blockIdx.x * blockDim.x + threadIdx.x;     // exact grid, no tail
    float4 a = __ldcs(reinterpret_cast<const float4*>(attn) + i4);
    int inner = i4 & (NHW/4 - 1);
    int bad   = i4 >> 13;
    int ba    = bad / ND;
    float4 dl = __ldg(reinterpret_cast<const float4*>(g_delta) + ba*(NHW/4) + inner);
    a.x += dl.x; a.y += dl.y; a.z += dl.z; a.w += dl.w;
    __stcs(reinterpret_cast<float4*>(out) + i4, a);
}

// ---------------------------------------------------------------------------
extern "C" void kernel_launch(void* const* d_in, const int* in_sizes, int n_in,
                              void* d_out, int out_size) {
    const float* attn_vol = (const float*)d_in[0];
    const float* feat     = (const float*)d_in[1];
    const float* dispgap  = (const float*)d_in[2];
    const float* Wq       = (const float*)d_in[3];
    const float* Wk       = (const float*)d_in[4];
    const float* Wv       = (const float*)d_in[5];
    const float* Wo       = (const float*)d_in[6];
    float* out = (float*)d_out;

    const int smem1 = KT*192*4 + KT*8*10*8;             // 30720 + 25600 = 56320 B
    const int smem2 = (CHUNK_F + NCATT*NEMB) * 4;       // 49920 + 2048  = 51968 B
    cudaFuncSetAttribute(qkv_proj_kernel,
                         cudaFuncAttributeMaxDynamicSharedMemorySize, smem1);
    cudaFuncSetAttribute(attn_kernel,
                         cudaFuncAttributeMaxDynamicSharedMemorySize, smem2);

    qkv_proj_kernel<<<dim3(NHW/K1P, NB), K1T, smem1>>>(feat, Wq, Wk, Wv);
    attn_kernel<<<dim3(NW/T2, NH, NB), T2, smem2>>>(dispgap, Wo);
    add_kernel<<<(NB*NCATT*ND*NHW/4)/256, 256>>>(attn_vol, out);
}